// round 5
// baseline (speedup 1.0000x reference)
#include <cuda_runtime.h>
#include <math.h>

#define TPB 128
#define WSTRIDE 36              // floats per token window (144B, vec4-aligned, conflict-free)
#define NEG_INF (-3.402823466e+38f)

__device__ __forceinline__ void cp_async16(void* smem_dst, const void* gmem_src) {
    unsigned saddr = (unsigned)__cvta_generic_to_shared(smem_dst);
    asm volatile("cp.async.ca.shared.global [%0], [%1], 16;\n"
                 :: "r"(saddr), "l"(gmem_src));
}
__device__ __forceinline__ void cp_async_commit_wait() {
    asm volatile("cp.async.commit_group;\n");
    asm volatile("cp.async.wait_group 0;\n" ::: "memory");
}

__global__ __launch_bounds__(TPB) void dfine_lqe_kernel(
    const float* __restrict__ scores,   // (tokens, 80)
    const float* __restrict__ pc,       // (tokens, 132)
    const float* __restrict__ W1,       // (20, 64)
    const float* __restrict__ b1,       // (64,)
    const float* __restrict__ W2,       // (64, 1)
    const float* __restrict__ b2,       // (1,)
    float* __restrict__ out,            // (tokens, 80)
    int tokens)
{
    __shared__ float sW1T[1280];        // transposed [j][d]
    __shared__ float sB1[64];
    __shared__ float sW2[64];
    __shared__ float sQ[TPB];
    extern __shared__ float sPC[];      // TPB * WSTRIDE floats

    const int tid = threadIdx.x;
    const int t0  = blockIdx.x * TPB;
    const int ntb = min(TPB, tokens - t0);

    // ---- stage weights (transpose W1 -> [j][d]) ----
    #pragma unroll 2
    for (int i = tid; i < 1280; i += TPB) {
        int d = i % 20;
        int j = i / 20;
        sW1T[i] = W1[d * 64 + j];
    }
    if (tid < 64) {
        sB1[tid] = b1[tid];
        sW2[tid] = W2[tid];
    }
    __syncthreads();

    float stat[20];
    const float4* pc4 = reinterpret_cast<const float4*>(pc);

    #pragma unroll
    for (int g = 0; g < 4; g++) {
        if (g) __syncthreads();                 // all readers done with prev stage

        // ---- coalesced async stage: 36-float window per token ----
        // window vec4 base within a row: (g*33)>>2 in {0,8,16,24}; group data at float offset g
        const size_t gbase = (size_t)t0 * 33 + ((g * 33) >> 2);
        #pragma unroll
        for (int s = 0; s < 9; s++) {
            int i   = tid + s * TPB;            // 0 .. 1151
            int row = i / 9;
            int v   = i - row * 9;
            if (row < ntb)
                cp_async16(&sPC[row * WSTRIDE + v * 4], &pc4[gbase + (size_t)row * 33 + v]);
        }
        cp_async_commit_wait();
        __syncthreads();                        // tile visible to all threads

        if (tid < ntb) {
            // pull window into registers (9x LDS.128, conflict-free: stride 36 floats)
            float buf[36];
            const float4* w4 = reinterpret_cast<const float4*>(&sPC[tid * WSTRIDE]);
            #pragma unroll
            for (int v = 0; v < 9; v++) {
                float4 t = w4[v];
                buf[v * 4 + 0] = t.x; buf[v * 4 + 1] = t.y;
                buf[v * 4 + 2] = t.z; buf[v * 4 + 3] = t.w;
            }

            // branchless running top-4 over buf[g .. g+32]
            float m0 = NEG_INF, m1 = NEG_INF, m2 = NEG_INF, m3 = NEG_INF;
            #pragma unroll
            for (int k = 0; k < 33; k++) {
                float v  = buf[g + k];
                float v1 = fminf(m0, v);  m0 = fmaxf(m0, v);
                float v2 = fminf(m1, v1); m1 = fmaxf(m1, v1);
                float v3 = fminf(m2, v2); m2 = fmaxf(m2, v2);
                m3 = fmaxf(m3, v3);
            }
            float s = 0.0f;
            #pragma unroll
            for (int k = 0; k < 33; k++) s += __expf(buf[g + k] - m0);
            float inv = 1.0f / s;
            float p0 = inv;
            float p1 = __expf(m1 - m0) * inv;
            float p2 = __expf(m2 - m0) * inv;
            float p3 = __expf(m3 - m0) * inv;
            stat[g * 5 + 0] = p0;
            stat[g * 5 + 1] = p1;
            stat[g * 5 + 2] = p2;
            stat[g * 5 + 3] = p3;
            stat[g * 5 + 4] = 0.25f * (p0 + p1 + p2 + p3);
        }
    }

    // ---- tiny MLP: q = W2 . relu(W1^T stat + b1) + b2 ----
    if (tid < ntb) {
        float q = b2[0];
        #pragma unroll 4
        for (int j = 0; j < 64; j++) {
            const float4* w4 = reinterpret_cast<const float4*>(&sW1T[j * 20]);
            float acc = sB1[j];
            float4 wa = w4[0], wb = w4[1], wc = w4[2], wd = w4[3], we = w4[4];
            acc = fmaf(stat[0],  wa.x, acc); acc = fmaf(stat[1],  wa.y, acc);
            acc = fmaf(stat[2],  wa.z, acc); acc = fmaf(stat[3],  wa.w, acc);
            acc = fmaf(stat[4],  wb.x, acc); acc = fmaf(stat[5],  wb.y, acc);
            acc = fmaf(stat[6],  wb.z, acc); acc = fmaf(stat[7],  wb.w, acc);
            acc = fmaf(stat[8],  wc.x, acc); acc = fmaf(stat[9],  wc.y, acc);
            acc = fmaf(stat[10], wc.z, acc); acc = fmaf(stat[11], wc.w, acc);
            acc = fmaf(stat[12], wd.x, acc); acc = fmaf(stat[13], wd.y, acc);
            acc = fmaf(stat[14], wd.z, acc); acc = fmaf(stat[15], wd.w, acc);
            acc = fmaf(stat[16], we.x, acc); acc = fmaf(stat[17], we.y, acc);
            acc = fmaf(stat[18], we.z, acc); acc = fmaf(stat[19], we.w, acc);
            q = fmaf(fmaxf(acc, 0.0f), sW2[j], q);
        }
        sQ[tid] = q;
    }
    __syncthreads();

    // ---- coalesced epilogue: out = scores + q[token], float4 ----
    {
        const float4* sc4  = reinterpret_cast<const float4*>(scores) + (size_t)t0 * 20;
        float4*       out4 = reinterpret_cast<float4*>(out) + (size_t)t0 * 20;
        const int nvec = ntb * 20;
        #pragma unroll 4
        for (int i = tid; i < nvec; i += TPB) {
            int row = i / 20;
            float4 s = sc4[i];
            float qq = sQ[row];
            s.x += qq; s.y += qq; s.z += qq; s.w += qq;
            out4[i] = s;
        }
    }
}

extern "C" void kernel_launch(void* const* d_in, const int* in_sizes, int n_in,
                              void* d_out, int out_size)
{
    const float* scores = (const float*)d_in[0];
    const float* pc     = (const float*)d_in[1];
    const float* W1     = (const float*)d_in[2];
    const float* b1     = (const float*)d_in[3];
    const float* W2     = (const float*)d_in[4];
    const float* b2     = (const float*)d_in[5];
    float* out = (float*)d_out;

    const int tokens = in_sizes[1] / 132;
    const int nblocks = (tokens + TPB - 1) / TPB;
    const size_t smem = TPB * WSTRIDE * sizeof(float);   // 18432 B dynamic

    dfine_lqe_kernel<<<nblocks, TPB, smem>>>(scores, pc, W1, b1, W2, b2, out, tokens);
}

// round 6
// speedup vs baseline: 1.0079x; 1.0079x over previous
#include <cuda_runtime.h>
#include <math.h>

#define TPB 128
#define WSTRIDE 36              // floats per token window (144B, vec4-aligned, LDS.128 conflict-free)
#define NEG_INF (-3.402823466e+38f)

__device__ __forceinline__ void cp_async16(void* smem_dst, const void* gmem_src) {
    unsigned saddr = (unsigned)__cvta_generic_to_shared(smem_dst);
    asm volatile("cp.async.ca.shared.global [%0], [%1], 16;\n"
                 :: "r"(saddr), "l"(gmem_src));
}
__device__ __forceinline__ void cp_async_commit_wait() {
    asm volatile("cp.async.commit_group;\n");
    asm volatile("cp.async.wait_group 0;\n" ::: "memory");
}

__global__ __launch_bounds__(TPB) void dfine_lqe_kernel(
    const float* __restrict__ scores,   // (tokens, 80)
    const float* __restrict__ pc,       // (tokens, 132)
    const float* __restrict__ W1,       // (20, 64)
    const float* __restrict__ b1,       // (64,)
    const float* __restrict__ W2,       // (64, 1)
    const float* __restrict__ b2,       // (1,)
    float* __restrict__ out,            // (tokens, 80)
    int tokens)
{
    __shared__ float sW1T[1280];        // transposed [j][d]
    __shared__ float sB1[64];
    __shared__ float sW2[64];
    __shared__ float sQ[TPB];
    extern __shared__ float sPC[];      // TPB * WSTRIDE floats (18432 B)

    const int tid = threadIdx.x;
    const int t0  = blockIdx.x * TPB;
    const int ntb = min(TPB, tokens - t0);

    // ---- stage weights (transpose W1 -> [j][d]) ----
    #pragma unroll 2
    for (int i = tid; i < 1280; i += TPB) {
        int d = i % 20;
        int j = i / 20;
        sW1T[i] = W1[d * 64 + j];
    }
    if (tid < 64) {
        sB1[tid] = b1[tid];
        sW2[tid] = W2[tid];
    }
    __syncthreads();

    float stat[20];
    const float4* pc4 = reinterpret_cast<const float4*>(pc);
    const float4* myw = reinterpret_cast<const float4*>(&sPC[tid * WSTRIDE]);

    #pragma unroll
    for (int g = 0; g < 4; g++) {
        if (g) __syncthreads();                 // readers done with prev stage

        // ---- coalesced async stage: 36-float window per token ----
        // row-major flat order: consecutive lanes -> consecutive 16B chunks
        const size_t gbase = (size_t)t0 * 33 + ((g * 33) >> 2);
        #pragma unroll
        for (int s = 0; s < 9; s++) {
            int i   = tid + s * TPB;            // 0 .. 1151
            int row = i / 9;
            int v   = i - row * 9;
            if (row < ntb)
                cp_async16(&sPC[row * WSTRIDE + v * 4], &pc4[gbase + (size_t)row * 33 + v]);
        }
        cp_async_commit_wait();
        __syncthreads();

        if (tid < ntb) {
            // valid window positions: [g, g+33). g is compile-time (full unroll).
            // PASS 1: branchless running top-4, streamed from smem (no reg buffer)
            float m0 = NEG_INF, m1 = NEG_INF, m2 = NEG_INF, m3 = NEG_INF;
            #pragma unroll
            for (int v = 0; v < 9; v++) {
                float4 t = myw[v];
                #pragma unroll
                for (int e = 0; e < 4; e++) {
                    int pos = v * 4 + e;
                    if (pos >= g && pos < g + 33) {
                        float val = (e == 0) ? t.x : (e == 1) ? t.y : (e == 2) ? t.z : t.w;
                        float v1 = fminf(m0, val); m0 = fmaxf(m0, val);
                        float v2 = fminf(m1, v1);  m1 = fmaxf(m1, v1);
                        float v3 = fminf(m2, v2);  m2 = fmaxf(m2, v2);
                        m3 = fmaxf(m3, v3);
                    }
                }
            }
            // PASS 2: softmax denominator, re-streamed from smem
            float ssum = 0.0f;
            #pragma unroll
            for (int v = 0; v < 9; v++) {
                float4 t = myw[v];
                #pragma unroll
                for (int e = 0; e < 4; e++) {
                    int pos = v * 4 + e;
                    if (pos >= g && pos < g + 33) {
                        float val = (e == 0) ? t.x : (e == 1) ? t.y : (e == 2) ? t.z : t.w;
                        ssum += __expf(val - m0);
                    }
                }
            }
            float inv = 1.0f / ssum;
            float p0 = inv;
            float p1 = __expf(m1 - m0) * inv;
            float p2 = __expf(m2 - m0) * inv;
            float p3 = __expf(m3 - m0) * inv;
            stat[g * 5 + 0] = p0;
            stat[g * 5 + 1] = p1;
            stat[g * 5 + 2] = p2;
            stat[g * 5 + 3] = p3;
            stat[g * 5 + 4] = 0.25f * (p0 + p1 + p2 + p3);
        }
    }

    // ---- tiny MLP: q = W2 . relu(W1^T stat + b1) + b2 ----
    if (tid < ntb) {
        float q = b2[0];
        #pragma unroll 4
        for (int j = 0; j < 64; j++) {
            const float4* w4 = reinterpret_cast<const float4*>(&sW1T[j * 20]);
            float acc = sB1[j];
            float4 wa = w4[0], wb = w4[1], wc = w4[2], wd = w4[3], we = w4[4];
            acc = fmaf(stat[0],  wa.x, acc); acc = fmaf(stat[1],  wa.y, acc);
            acc = fmaf(stat[2],  wa.z, acc); acc = fmaf(stat[3],  wa.w, acc);
            acc = fmaf(stat[4],  wb.x, acc); acc = fmaf(stat[5],  wb.y, acc);
            acc = fmaf(stat[6],  wb.z, acc); acc = fmaf(stat[7],  wb.w, acc);
            acc = fmaf(stat[8],  wc.x, acc); acc = fmaf(stat[9],  wc.y, acc);
            acc = fmaf(stat[10], wc.z, acc); acc = fmaf(stat[11], wc.w, acc);
            acc = fmaf(stat[12], wd.x, acc); acc = fmaf(stat[13], wd.y, acc);
            acc = fmaf(stat[14], wd.z, acc); acc = fmaf(stat[15], wd.w, acc);
            acc = fmaf(stat[16], we.x, acc); acc = fmaf(stat[17], we.y, acc);
            acc = fmaf(stat[18], we.z, acc); acc = fmaf(stat[19], we.w, acc);
            q = fmaf(fmaxf(acc, 0.0f), sW2[j], q);
        }
        sQ[tid] = q;
    }
    __syncthreads();

    // ---- coalesced epilogue: out = scores + q[token], float4 ----
    {
        const float4* sc4  = reinterpret_cast<const float4*>(scores) + (size_t)t0 * 20;
        float4*       out4 = reinterpret_cast<float4*>(out) + (size_t)t0 * 20;
        const int nvec = ntb * 20;
        #pragma unroll 4
        for (int i = tid; i < nvec; i += TPB) {
            int row = i / 20;
            float4 s = sc4[i];
            float qq = sQ[row];
            s.x += qq; s.y += qq; s.z += qq; s.w += qq;
            out4[i] = s;
        }
    }
}

extern "C" void kernel_launch(void* const* d_in, const int* in_sizes, int n_in,
                              void* d_out, int out_size)
{
    const float* scores = (const float*)d_in[0];
    const float* pc     = (const float*)d_in[1];
    const float* W1     = (const float*)d_in[2];
    const float* b1     = (const float*)d_in[3];
    const float* W2     = (const float*)d_in[4];
    const float* b2     = (const float*)d_in[5];
    float* out = (float*)d_out;

    const int tokens = in_sizes[1] / 132;
    const int nblocks = (tokens + TPB - 1) / TPB;
    const size_t smem = TPB * WSTRIDE * sizeof(float);   // 18432 B dynamic

    dfine_lqe_kernel<<<nblocks, TPB, smem>>>(scores, pc, W1, b1, W2, b2, out, tokens);
}